// round 15
// baseline (speedup 1.0000x reference)
#include <cuda_runtime.h>
#include <cuda_bf16.h>
#include <cstdint>
#include <cstddef>

#define E_N 1000000
#define V_N 200000

// ---------------- device scratch (allocation-free rule) ----------------
__device__ __align__(128) float g_agg[(size_t)V_N * 256];
// n-major bf16 weights, hi|lo concatenated along k: W'[n][2K]
__device__ __align__(128) __nv_bfloat16 g_w1m_p[256 * 320];   // K=160 (145 valid)
__device__ __align__(128) __nv_bfloat16 g_w2m_p[256 * 512];   // K=256
__device__ __align__(128) __nv_bfloat16 g_w1a_p[256 * 512];   // K=256
__device__ __align__(128) __nv_bfloat16 g_w2a_p[128 * 512];   // K=256, N=128

// ---------------- smem layout (bytes) ----------------
// A/h1/h2 region: 128 x 520 bf16 = 133120 (also reused as 128 x 260 fp32)
// B ring: 3 stages x [256 rows x stride 56 bf16] = 3 x 28672
#define B_OFF     133120
#define B_STAGE   28672
#define B_STRIDE  56              // bf16 elems; 112 B: conflict-free ldmatrix phases
#define BIAS_OFF  219136          // 256 floats
#define AUX_OFF   220160          // svi[128] (edge) or Wc[256] floats (var)
#define SMEM_TOTAL 221184

__device__ __forceinline__ uint32_t smem_u32_of(const void* p) {
    uint32_t a;
    asm("{ .reg .u64 t; cvta.to.shared.u64 t, %1; cvt.u32.u64 %0, t; }" : "=r"(a) : "l"(p));
    return a;
}
__device__ __forceinline__ void ldsm4(uint32_t* r, uint32_t addr) {
    asm volatile("ldmatrix.sync.aligned.m8n8.x4.shared.b16 {%0,%1,%2,%3}, [%4];"
                 : "=r"(r[0]), "=r"(r[1]), "=r"(r[2]), "=r"(r[3]) : "r"(addr));
}
__device__ __forceinline__ void mma16816(float* c, const uint32_t* a, const uint32_t* b) {
    asm volatile("mma.sync.aligned.m16n8k16.row.col.f32.bf16.bf16.f32 "
                 "{%0,%1,%2,%3}, {%4,%5,%6,%7}, {%8,%9}, {%0,%1,%2,%3};"
                 : "+f"(c[0]), "+f"(c[1]), "+f"(c[2]), "+f"(c[3])
                 : "r"(a[0]), "r"(a[1]), "r"(a[2]), "r"(a[3]), "r"(b[0]), "r"(b[1]));
}
__device__ __forceinline__ void cpa16(uint32_t dst, const void* src) {
    asm volatile("cp.async.cg.shared.global [%0], [%1], 16;" :: "r"(dst), "l"(src) : "memory");
}
#define CP_COMMIT() asm volatile("cp.async.commit_group;" ::: "memory")

__device__ __forceinline__ float lsig(float x) {
    return fminf(x, 0.0f) - __logf(1.0f + __expf(-fabsf(x)));
}
// split fp32 pair (a,b) -> bf16x2 hi (a in low 16) and bf16x2 lo
__device__ __forceinline__ void cvt2(float a, float b, uint32_t& h, uint32_t& l) {
    __nv_bfloat16 ah = __float2bfloat16(a), bh = __float2bfloat16(b);
    __nv_bfloat16 al = __float2bfloat16(a - __bfloat162float(ah));
    __nv_bfloat16 bl = __float2bfloat16(b - __bfloat162float(bh));
    h = ((uint32_t)__bfloat16_as_ushort(bh) << 16) | (uint32_t)__bfloat16_as_ushort(ah);
    l = ((uint32_t)__bfloat16_as_ushort(bl) << 16) | (uint32_t)__bfloat16_as_ushort(al);
}

// ---------------- prep: fp32 W[N][Kv] -> bf16 W'[n][2K] hi|lo, zero-padded ----------------
__global__ void prep_w_kernel(const float* __restrict__ src, int which, int N, int Kv, int K) {
    int i = blockIdx.x * 256 + threadIdx.x;
    if (i >= N * K) return;
    __nv_bfloat16* dst = (which == 0) ? g_w1m_p : (which == 1) ? g_w2m_p
                       : (which == 2) ? g_w1a_p : g_w2a_p;
    int n = i / K, k = i % K;
    float v = (k < Kv) ? __ldg(src + (size_t)n * Kv + k) : 0.f;
    __nv_bfloat16 h = __float2bfloat16(v);
    __nv_bfloat16 l = __float2bfloat16(v - __bfloat162float(h));
    dst[(size_t)n * 2 * K + k]     = h;
    dst[(size_t)n * 2 * K + K + k] = l;
}

__global__ void zero_agg_kernel() {
    size_t idx = (size_t)blockIdx.x * blockDim.x + threadIdx.x;
    reinterpret_cast<float4*>(g_agg)[idx] = make_float4(0.f, 0.f, 0.f, 0.f);
}

// ---------------- fused-pass hi/lo GEMM, warp tile 64x64, 3-stage ring ----------------
// A smem: [128][2K] bf16 stride astr (hi cols 0..K-1, lo K..2K-1)
// B global: W'[n][2K]. Chunk sequence g=0..2NC-1:
//   g <  NC : Bh chunk kc=g    -> mma Ah*Bh AND Al*Bh (fused, B resident once)
//   g >= NC : Bl chunk kc=g-NC -> mma Ah*Bl
// 8 warps (256 thr): wm = wid&1 (2 x 64 rows), wn = wid>>1 (4 x 64 cols); mt=4, NTILES<=8
template <int NTILES>
__device__ __forceinline__ void gemm3(
    const __nv_bfloat16* __restrict__ Bg, int K, int NC, int Nrows,
    uint32_t aBase, int astr, uint32_t bBase,
    int wm, int wn, int lane, int tid, float acc[4][NTILES][4])
{
    const int TOT = 2 * NC;
    auto issue = [&](int g, int slot) {
        int fu = (g < NC);
        int kc = fu ? g : g - NC;
        int boff = fu ? 0 : K;
        for (int idx = tid; idx < Nrows * 4; idx += 256) {
            int n = idx >> 2, seg = idx & 3;
            const char* src = (const char*)Bg
                + (((size_t)n * 2 * K) + boff + kc * 32 + seg * 8) * 2;
            cpa16(bBase + slot * B_STAGE + n * (B_STRIDE * 2) + seg * 16, src);
        }
        CP_COMMIT();
    };

    issue(0, 0);
    issue(1, 1);
#pragma unroll 1
    for (int g = 0; g < TOT; g++) {
        int slot = g % 3;
        asm volatile("cp.async.wait_group 1;" ::: "memory");   // stage g resident
        __syncthreads();                                       // visibility + ring reuse safety
        if (g + 2 < TOT) issue(g + 2, (g + 2) % 3);

        bool fu = (g < NC);
        int kc = fu ? g : g - NC;
        uint32_t bStage = bBase + slot * B_STAGE;
#pragma unroll
        for (int ks = 0; ks < 32; ks += 16) {
            int acol = kc * 32 + ks;
            uint32_t ah[4][4];
#pragma unroll
            for (int mt = 0; mt < 4; mt++) {
                uint32_t ad = aBase
                    + (uint32_t)((wm * 64 + mt * 16 + (lane & 15)) * astr + acol) * 2
                    + ((lane >> 4) << 4);
                ldsm4(ah[mt], ad);
            }
            uint32_t b[NTILES][2];
#pragma unroll
            for (int p = 0; p < NTILES / 2; p++) {
                int grp = lane >> 3;
                int nrow = wn * (NTILES * 8) + p * 16 + ((grp >> 1) << 3) + (lane & 7);
                int kk = ks + ((grp & 1) << 3);
                uint32_t t[4];
                ldsm4(t, bStage + nrow * (B_STRIDE * 2) + kk * 2);
                b[2 * p][0] = t[0]; b[2 * p][1] = t[1];
                b[2 * p + 1][0] = t[2]; b[2 * p + 1][1] = t[3];
            }
#pragma unroll
            for (int mt = 0; mt < 4; mt++)
#pragma unroll
                for (int nt = 0; nt < NTILES; nt++)
                    mma16816(acc[mt][nt], ah[mt], b[nt]);
            if (fu) {                       // A-lo pass against the SAME resident Bh
                uint32_t al[4][4];
#pragma unroll
                for (int mt = 0; mt < 4; mt++) {
                    uint32_t ad = aBase
                        + (uint32_t)((wm * 64 + mt * 16 + (lane & 15)) * astr + K + acol) * 2
                        + ((lane >> 4) << 4);
                    ldsm4(al[mt], ad);
                }
#pragma unroll
                for (int mt = 0; mt < 4; mt++)
#pragma unroll
                    for (int nt = 0; nt < NTILES; nt++)
                        mma16816(acc[mt][nt], al[mt], b[nt]);
            }
        }
    }
    __syncthreads();   // callers reuse A region right after
}

// GEMM1 epilogue: acc -> lsig(+bias) -> h1 hi/lo bf16 in A region ([128][520], lo at +256)
__device__ __forceinline__ void epi_h1(float acc[4][8][4], const float* bias,
                                       char* smx, int wm, int wn, int lane) {
#pragma unroll
    for (int mt = 0; mt < 4; mt++)
#pragma unroll
        for (int nt = 0; nt < 8; nt++) {
            int row = wm * 64 + mt * 16 + (lane >> 2);
            int col = wn * 64 + nt * 8 + 2 * (lane & 3);
            uint32_t hh, ll;
            float a0 = lsig(acc[mt][nt][0] + bias[col]);
            float a1 = lsig(acc[mt][nt][1] + bias[col + 1]);
            cvt2(a0, a1, hh, ll);
            *(uint32_t*)(smx + (row * 520 + col) * 2) = hh;
            *(uint32_t*)(smx + (row * 520 + 256 + col) * 2) = ll;
            float a2 = lsig(acc[mt][nt][2] + bias[col]);
            float a3 = lsig(acc[mt][nt][3] + bias[col + 1]);
            cvt2(a2, a3, hh, ll);
            *(uint32_t*)(smx + ((row + 8) * 520 + col) * 2) = hh;
            *(uint32_t*)(smx + ((row + 8) * 520 + 256 + col) * 2) = ll;
        }
}

// ---------------- edge kernel: X -> MLP(145,256,256) -> RED scatter ----------------
__global__ __launch_bounds__(256, 1) void edge_kernel(
    const float* __restrict__ vs, const float* __restrict__ ef,
    const float* __restrict__ sol, const float* __restrict__ b1m,
    const int* __restrict__ vidx, const int* __restrict__ esign)
{
    extern __shared__ char smx[];
    uint32_t sb = smem_u32_of(smx);
    const int tid = threadIdx.x, lane = tid & 31, wid = tid >> 5;
    const int wm = wid & 1, wn = wid >> 1;
    const size_t ebase = (size_t)blockIdx.x * 128;
    float* bias = (float*)(smx + BIAS_OFF);
    int* svi = (int*)(smx + AUX_OFF);

    if (tid < 128) ((float2*)bias)[tid] = ((const float2*)b1m)[tid];

    // ---- stage A = [state|ef|signed|pad] hi/lo into [128][328] bf16 ----
    for (int idx = tid; idx < 128 * 80; idx += 256) {
        int row = idx / 80, p = idx - row * 80, c0 = 2 * p;
        size_t grow = ebase + row;
        bool ok = grow < (size_t)E_N;
        float v0 = 0.f, v1 = 0.f;
        if (ok) {
            if (c0 < 128) { float2 t = __ldg((const float2*)(vs + grow * 128 + c0)); v0 = t.x; v1 = t.y; }
            else if (c0 < 144) { float2 t = __ldg((const float2*)(ef + grow * 16 + (c0 - 128))); v0 = t.x; v1 = t.y; }
            else if (c0 == 144) {
                int vi = __ldg(vidx + grow);
                svi[row] = vi;
                v0 = (float)__ldg(esign + grow) * __ldg(sol + vi);
            }
        } else if (c0 == 144) svi[row] = 0;
        uint32_t hh, ll;
        cvt2(v0, v1, hh, ll);
        *(uint32_t*)(smx + (row * 328 + c0) * 2) = hh;
        *(uint32_t*)(smx + (row * 328 + 160 + c0) * 2) = ll;
    }

    float acc[4][8][4];
#pragma unroll
    for (int i = 0; i < 4; i++)
#pragma unroll
        for (int j = 0; j < 8; j++)
#pragma unroll
            for (int q = 0; q < 4; q++) acc[i][j][q] = 0.f;

    // GEMM1: K=160, NC=5  (A stride 328)
    gemm3<8>(g_w1m_p, 160, 5, 256, sb, 328, sb + B_OFF, wm, wn, lane, tid, acc);
    epi_h1(acc, bias, smx, wm, wn, lane);
#pragma unroll
    for (int i = 0; i < 4; i++)
#pragma unroll
        for (int j = 0; j < 8; j++)
#pragma unroll
            for (int q = 0; q < 4; q++) acc[i][j][q] = 0.f;

    // GEMM2: K=256, NC=8 (A = h1, stride 520); internal first sync covers epi writes
    gemm3<8>(g_w2m_p, 256, 8, 256, sb, 520, sb + B_OFF, wm, wn, lane, tid, acc);

    // epilogue: lsig -> fp32 h2 [128][260] in A region
    float* h2f = (float*)smx;
#pragma unroll
    for (int mt = 0; mt < 4; mt++)
#pragma unroll
        for (int nt = 0; nt < 8; nt++) {
            int row = wm * 64 + mt * 16 + (lane >> 2);
            int col = wn * 64 + nt * 8 + 2 * (lane & 3);
            h2f[row * 260 + col]     = lsig(acc[mt][nt][0]);
            h2f[row * 260 + col + 1] = lsig(acc[mt][nt][1]);
            h2f[(row + 8) * 260 + col]     = lsig(acc[mt][nt][2]);
            h2f[(row + 8) * 260 + col + 1] = lsig(acc[mt][nt][3]);
        }
    __syncthreads();

    // coalesced vector-RED scatter
    for (int i = tid; i < 128 * 64; i += 256) {
        int row = i >> 6, seg = i & 63;
        if (ebase + row < (size_t)E_N) {
            float4 v = *(float4*)(h2f + row * 260 + seg * 4);
            atomicAdd((float4*)(g_agg + (size_t)svi[row] * 256 + seg * 4), v);
        }
    }
}

// ---------------- var kernel: g_agg -> MLP(256,256,128) -> classifier(128,2) ----------------
__global__ __launch_bounds__(256, 1) void var_kernel(
    const float* __restrict__ b1a, const float* __restrict__ Wc,
    const float* __restrict__ bc, float* __restrict__ out)
{
    extern __shared__ char smx[];
    uint32_t sb = smem_u32_of(smx);
    const int tid = threadIdx.x, lane = tid & 31, wid = tid >> 5;
    const int wm = wid & 1, wn = wid >> 1;
    const size_t vb = (size_t)blockIdx.x * 128;
    float* bias = (float*)(smx + BIAS_OFF);
    float* wc = (float*)(smx + AUX_OFF);

    if (tid < 128) {
        ((float2*)bias)[tid] = ((const float2*)b1a)[tid];
        ((float2*)wc)[tid]   = ((const float2*)Wc)[tid];
    }

    // ---- stage A = g_agg rows hi/lo into [128][520] ----
    for (int idx = tid; idx < 128 * 128; idx += 256) {
        int row = idx >> 7, p = idx & 127, c0 = 2 * p;
        size_t gv = vb + row;
        float2 t = (gv < (size_t)V_N) ? *(const float2*)(g_agg + gv * 256 + c0)
                                      : make_float2(0.f, 0.f);
        uint32_t hh, ll;
        cvt2(t.x, t.y, hh, ll);
        *(uint32_t*)(smx + (row * 520 + c0) * 2) = hh;
        *(uint32_t*)(smx + (row * 520 + 256 + c0) * 2) = ll;
    }

    float acc[4][8][4];
#pragma unroll
    for (int i = 0; i < 4; i++)
#pragma unroll
        for (int j = 0; j < 8; j++)
#pragma unroll
            for (int q = 0; q < 4; q++) acc[i][j][q] = 0.f;

    // GEMM1: K=256, NC=8
    gemm3<8>(g_w1a_p, 256, 8, 256, sb, 520, sb + B_OFF, wm, wn, lane, tid, acc);
    epi_h1(acc, bias, smx, wm, wn, lane);

    // GEMM2: N=128, K=256 (warp tile 64x32)
    float acc2[4][4][4];
#pragma unroll
    for (int i = 0; i < 4; i++)
#pragma unroll
        for (int j = 0; j < 4; j++)
#pragma unroll
            for (int q = 0; q < 4; q++) acc2[i][j][q] = 0.f;
    gemm3<4>(g_w2a_p, 256, 8, 128, sb, 520, sb + B_OFF, wm, wn, lane, tid, acc2);

    // epilogue: lsig -> fp32 h2 [128][132]
    float* h2f = (float*)smx;
#pragma unroll
    for (int mt = 0; mt < 4; mt++)
#pragma unroll
        for (int nt = 0; nt < 4; nt++) {
            int row = wm * 64 + mt * 16 + (lane >> 2);
            int col = wn * 32 + nt * 8 + 2 * (lane & 3);
            h2f[row * 132 + col]     = lsig(acc2[mt][nt][0]);
            h2f[row * 132 + col + 1] = lsig(acc2[mt][nt][1]);
            h2f[(row + 8) * 132 + col]     = lsig(acc2[mt][nt][2]);
            h2f[(row + 8) * 132 + col + 1] = lsig(acc2[mt][nt][3]);
        }
    __syncthreads();

    // classifier: 256 threads cover all 128 rows x 2 outputs exactly once
    {
        int row = tid >> 1, p = tid & 1;
        float s = __ldg(bc + p);
        const float* wcp = wc + p * 128;
        const float* hr = h2f + row * 132;
#pragma unroll 8
        for (int j = 0; j < 128; j++) s = fmaf(hr[j], wcp[j], s);
        size_t gv = vb + row;
        if (gv < (size_t)V_N) out[gv * 2 + p] = s;
    }
}

// ---------------- launch ----------------
extern "C" void kernel_launch(void* const* d_in, const int* in_sizes, int n_in,
                              void* d_out, int out_size)
{
    const float* vs   = (const float*)d_in[0];
    const float* ef   = (const float*)d_in[1];
    const float* sol  = (const float*)d_in[2];
    const float* W1m  = (const float*)d_in[3];
    const float* b1m  = (const float*)d_in[4];
    const float* W2m  = (const float*)d_in[5];
    const float* W1a  = (const float*)d_in[6];
    const float* b1a  = (const float*)d_in[7];
    const float* W2a  = (const float*)d_in[8];
    const float* Wc   = (const float*)d_in[9];
    const float* bc   = (const float*)d_in[10];
    const int*  vidx  = (const int*)d_in[11];
    const int*  esign = (const int*)d_in[12];
    float* out = (float*)d_out;

    cudaFuncSetAttribute(edge_kernel, cudaFuncAttributeMaxDynamicSharedMemorySize, SMEM_TOTAL);
    cudaFuncSetAttribute(var_kernel,  cudaFuncAttributeMaxDynamicSharedMemorySize, SMEM_TOTAL);

    prep_w_kernel<<<(256 * 160 + 255) / 256, 256>>>(W1m, 0, 256, 145, 160);
    prep_w_kernel<<<(256 * 256 + 255) / 256, 256>>>(W2m, 1, 256, 256, 256);
    prep_w_kernel<<<(256 * 256 + 255) / 256, 256>>>(W1a, 2, 256, 256, 256);
    prep_w_kernel<<<(128 * 256 + 255) / 256, 256>>>(W2a, 3, 128, 256, 256);
    zero_agg_kernel<<<50000, 256>>>();
    edge_kernel<<<(E_N + 127) / 128, 256, SMEM_TOTAL>>>(vs, ef, sol, b1m, vidx, esign);
    var_kernel<<<(V_N + 127) / 128, 256, SMEM_TOTAL>>>(b1a, Wc, bc, out);
}

// round 16
// speedup vs baseline: 1.2536x; 1.2536x over previous
#include <cuda_runtime.h>
#include <cuda_bf16.h>
#include <cstdint>
#include <cstddef>

#define E_N 1000000
#define V_N 200000

// ---------------- device scratch (allocation-free rule) ----------------
__device__ __align__(128) float g_agg[(size_t)V_N * 256];
// n-major bf16 weights, hi|lo concatenated along k: W'[n][2K]
__device__ __align__(128) __nv_bfloat16 g_w1m_p[256 * 320];   // K=160 (145 valid)
__device__ __align__(128) __nv_bfloat16 g_w2m_p[256 * 512];   // K=256
__device__ __align__(128) __nv_bfloat16 g_w1a_p[256 * 512];   // K=256
__device__ __align__(128) __nv_bfloat16 g_w2a_p[128 * 512];   // K=256, N=128

// ---------------- smem layout (bytes) ----------------
// A/h1/h2 region: 128 x 520 bf16 = 133120 (also reused as 128 x 260 fp32)
// B ring: 3 stages x [256 rows x stride 56 bf16] = 3 x 28672
#define B_OFF     133120
#define B_STAGE   28672
#define B_STRIDE  56              // bf16 elems; 112 B: conflict-free ldmatrix phases
#define BIAS_OFF  219136          // 256 floats
#define AUX_OFF   220160          // svi[128] (edge) or Wc[256] floats (var)
#define SMEM_TOTAL 221184

__device__ __forceinline__ uint32_t smem_u32_of(const void* p) {
    uint32_t a;
    asm("{ .reg .u64 t; cvta.to.shared.u64 t, %1; cvt.u32.u64 %0, t; }" : "=r"(a) : "l"(p));
    return a;
}
__device__ __forceinline__ void ldsm4(uint32_t* r, uint32_t addr) {
    asm volatile("ldmatrix.sync.aligned.m8n8.x4.shared.b16 {%0,%1,%2,%3}, [%4];"
                 : "=r"(r[0]), "=r"(r[1]), "=r"(r[2]), "=r"(r[3]) : "r"(addr));
}
__device__ __forceinline__ void mma16816(float* c, const uint32_t* a, const uint32_t* b) {
    asm volatile("mma.sync.aligned.m16n8k16.row.col.f32.bf16.bf16.f32 "
                 "{%0,%1,%2,%3}, {%4,%5,%6,%7}, {%8,%9}, {%0,%1,%2,%3};"
                 : "+f"(c[0]), "+f"(c[1]), "+f"(c[2]), "+f"(c[3])
                 : "r"(a[0]), "r"(a[1]), "r"(a[2]), "r"(a[3]), "r"(b[0]), "r"(b[1]));
}
__device__ __forceinline__ void cpa16(uint32_t dst, const void* src) {
    asm volatile("cp.async.cg.shared.global [%0], [%1], 16;" :: "r"(dst), "l"(src) : "memory");
}
#define CP_COMMIT() asm volatile("cp.async.commit_group;" ::: "memory")

__device__ __forceinline__ float lsig(float x) {
    return fminf(x, 0.0f) - __logf(1.0f + __expf(-fabsf(x)));
}
// split fp32 pair (a,b) -> bf16x2 hi (a in low 16) and bf16x2 lo
__device__ __forceinline__ void cvt2(float a, float b, uint32_t& h, uint32_t& l) {
    __nv_bfloat16 ah = __float2bfloat16(a), bh = __float2bfloat16(b);
    __nv_bfloat16 al = __float2bfloat16(a - __bfloat162float(ah));
    __nv_bfloat16 bl = __float2bfloat16(b - __bfloat162float(bh));
    h = ((uint32_t)__bfloat16_as_ushort(bh) << 16) | (uint32_t)__bfloat16_as_ushort(ah);
    l = ((uint32_t)__bfloat16_as_ushort(bl) << 16) | (uint32_t)__bfloat16_as_ushort(al);
}

// ---------------- prep: fp32 W[N][Kv] -> bf16 W'[n][2K] hi|lo, zero-padded ----------------
__global__ void prep_w_kernel(const float* __restrict__ src, int which, int N, int Kv, int K) {
    int i = blockIdx.x * 256 + threadIdx.x;
    if (i >= N * K) return;
    __nv_bfloat16* dst = (which == 0) ? g_w1m_p : (which == 1) ? g_w2m_p
                       : (which == 2) ? g_w1a_p : g_w2a_p;
    int n = i / K, k = i % K;
    float v = (k < Kv) ? __ldg(src + (size_t)n * Kv + k) : 0.f;
    __nv_bfloat16 h = __float2bfloat16(v);
    __nv_bfloat16 l = __float2bfloat16(v - __bfloat162float(h));
    dst[(size_t)n * 2 * K + k]     = h;
    dst[(size_t)n * 2 * K + K + k] = l;
}

__global__ void zero_agg_kernel() {
    size_t idx = (size_t)blockIdx.x * blockDim.x + threadIdx.x;
    reinterpret_cast<float4*>(g_agg)[idx] = make_float4(0.f, 0.f, 0.f, 0.f);
}

// ---------------- fused-pass hi/lo GEMM, 512 thr, warp tile 32x64, 3-stage ring ----------
// A smem: [128][2K] bf16 stride astr (hi cols 0..K-1, lo K..2K-1)
// B global: W'[n][2K]. Chunk sequence g=0..2NC-1:
//   g <  NC : Bh chunk kc=g    -> mma Ah*Bh AND Al*Bh (fused, B resident once)
//   g >= NC : Bl chunk kc=g-NC -> mma Ah*Bl
// 16 warps: wm = wid&3 (4 x 32 rows), wn = wid>>2 (4 x NTILES*8 cols)
template <int NTILES>
__device__ __forceinline__ void gemm3(
    const __nv_bfloat16* __restrict__ Bg, int K, int NC, int Nrows,
    uint32_t aBase, int astr, uint32_t bBase,
    int wm, int wn, int lane, int tid, float acc[2][NTILES][4])
{
    const int TOT = 2 * NC;
    auto issue = [&](int g, int slot) {
        int fu = (g < NC);
        int kc = fu ? g : g - NC;
        int boff = fu ? 0 : K;
        for (int idx = tid; idx < Nrows * 4; idx += 512) {
            int n = idx >> 2, seg = idx & 3;
            const char* src = (const char*)Bg
                + (((size_t)n * 2 * K) + boff + kc * 32 + seg * 8) * 2;
            cpa16(bBase + slot * B_STAGE + n * (B_STRIDE * 2) + seg * 16, src);
        }
        CP_COMMIT();
    };

    issue(0, 0);
    issue(1, 1);
#pragma unroll 1
    for (int g = 0; g < TOT; g++) {
        int slot = g % 3;
        asm volatile("cp.async.wait_group 1;" ::: "memory");   // stage g resident
        __syncthreads();                                       // visibility + ring reuse safety
        if (g + 2 < TOT) issue(g + 2, (g + 2) % 3);

        bool fu = (g < NC);
        int kc = fu ? g : g - NC;
        uint32_t bStage = bBase + slot * B_STAGE;
#pragma unroll
        for (int ks = 0; ks < 32; ks += 16) {
            int acol = kc * 32 + ks;
            uint32_t ah[2][4];
#pragma unroll
            for (int mt = 0; mt < 2; mt++) {
                uint32_t ad = aBase
                    + (uint32_t)((wm * 32 + mt * 16 + (lane & 15)) * astr + acol) * 2
                    + ((lane >> 4) << 4);
                ldsm4(ah[mt], ad);
            }
            uint32_t b[NTILES][2];
#pragma unroll
            for (int p = 0; p < NTILES / 2; p++) {
                int grp = lane >> 3;
                int nrow = wn * (NTILES * 8) + p * 16 + ((grp >> 1) << 3) + (lane & 7);
                int kk = ks + ((grp & 1) << 3);
                uint32_t t[4];
                ldsm4(t, bStage + nrow * (B_STRIDE * 2) + kk * 2);
                b[2 * p][0] = t[0]; b[2 * p][1] = t[1];
                b[2 * p + 1][0] = t[2]; b[2 * p + 1][1] = t[3];
            }
#pragma unroll
            for (int mt = 0; mt < 2; mt++)
#pragma unroll
                for (int nt = 0; nt < NTILES; nt++)
                    mma16816(acc[mt][nt], ah[mt], b[nt]);
            if (fu) {                       // A-lo pass against the SAME resident Bh
                uint32_t al[2][4];
#pragma unroll
                for (int mt = 0; mt < 2; mt++) {
                    uint32_t ad = aBase
                        + (uint32_t)((wm * 32 + mt * 16 + (lane & 15)) * astr + K + acol) * 2
                        + ((lane >> 4) << 4);
                    ldsm4(al[mt], ad);
                }
#pragma unroll
                for (int mt = 0; mt < 2; mt++)
#pragma unroll
                    for (int nt = 0; nt < NTILES; nt++)
                        mma16816(acc[mt][nt], al[mt], b[nt]);
            }
        }
    }
    __syncthreads();   // callers reuse A region right after
}

// GEMM1 epilogue: acc -> lsig(+bias) -> h1 hi/lo bf16 in A region ([128][520], lo at +256)
__device__ __forceinline__ void epi_h1(float acc[2][8][4], const float* bias,
                                       char* smx, int wm, int wn, int lane) {
#pragma unroll
    for (int mt = 0; mt < 2; mt++)
#pragma unroll
        for (int nt = 0; nt < 8; nt++) {
            int row = wm * 32 + mt * 16 + (lane >> 2);
            int col = wn * 64 + nt * 8 + 2 * (lane & 3);
            uint32_t hh, ll;
            float a0 = lsig(acc[mt][nt][0] + bias[col]);
            float a1 = lsig(acc[mt][nt][1] + bias[col + 1]);
            cvt2(a0, a1, hh, ll);
            *(uint32_t*)(smx + (row * 520 + col) * 2) = hh;
            *(uint32_t*)(smx + (row * 520 + 256 + col) * 2) = ll;
            float a2 = lsig(acc[mt][nt][2] + bias[col]);
            float a3 = lsig(acc[mt][nt][3] + bias[col + 1]);
            cvt2(a2, a3, hh, ll);
            *(uint32_t*)(smx + ((row + 8) * 520 + col) * 2) = hh;
            *(uint32_t*)(smx + ((row + 8) * 520 + 256 + col) * 2) = ll;
        }
}

// ---------------- edge kernel: X -> MLP(145,256,256) -> RED scatter ----------------
__global__ __launch_bounds__(512, 1) void edge_kernel(
    const float* __restrict__ vs, const float* __restrict__ ef,
    const float* __restrict__ sol, const float* __restrict__ b1m,
    const int* __restrict__ vidx, const int* __restrict__ esign)
{
    extern __shared__ char smx[];
    uint32_t sb = smem_u32_of(smx);
    const int tid = threadIdx.x, lane = tid & 31, wid = tid >> 5;
    const int wm = wid & 3, wn = wid >> 2;
    const size_t ebase = (size_t)blockIdx.x * 128;
    float* bias = (float*)(smx + BIAS_OFF);
    int* svi = (int*)(smx + AUX_OFF);

    if (tid < 128) ((float2*)bias)[tid] = ((const float2*)b1m)[tid];

    // ---- stage A = [state|ef|signed|pad] hi/lo into [128][328] bf16 ----
    for (int idx = tid; idx < 128 * 80; idx += 512) {
        int row = idx / 80, p = idx - row * 80, c0 = 2 * p;
        size_t grow = ebase + row;
        bool ok = grow < (size_t)E_N;
        float v0 = 0.f, v1 = 0.f;
        if (ok) {
            if (c0 < 128) { float2 t = __ldg((const float2*)(vs + grow * 128 + c0)); v0 = t.x; v1 = t.y; }
            else if (c0 < 144) { float2 t = __ldg((const float2*)(ef + grow * 16 + (c0 - 128))); v0 = t.x; v1 = t.y; }
            else if (c0 == 144) {
                int vi = __ldg(vidx + grow);
                svi[row] = vi;
                v0 = (float)__ldg(esign + grow) * __ldg(sol + vi);
            }
        } else if (c0 == 144) svi[row] = 0;
        uint32_t hh, ll;
        cvt2(v0, v1, hh, ll);
        *(uint32_t*)(smx + (row * 328 + c0) * 2) = hh;
        *(uint32_t*)(smx + (row * 328 + 160 + c0) * 2) = ll;
    }

    float acc[2][8][4];
#pragma unroll
    for (int i = 0; i < 2; i++)
#pragma unroll
        for (int j = 0; j < 8; j++)
#pragma unroll
            for (int q = 0; q < 4; q++) acc[i][j][q] = 0.f;

    // GEMM1: K=160, NC=5  (A stride 328)
    gemm3<8>(g_w1m_p, 160, 5, 256, sb, 328, sb + B_OFF, wm, wn, lane, tid, acc);
    epi_h1(acc, bias, smx, wm, wn, lane);
#pragma unroll
    for (int i = 0; i < 2; i++)
#pragma unroll
        for (int j = 0; j < 8; j++)
#pragma unroll
            for (int q = 0; q < 4; q++) acc[i][j][q] = 0.f;

    // GEMM2: K=256, NC=8 (A = h1, stride 520); internal first sync covers epi writes
    gemm3<8>(g_w2m_p, 256, 8, 256, sb, 520, sb + B_OFF, wm, wn, lane, tid, acc);

    // epilogue: lsig -> fp32 h2 [128][260] in A region
    float* h2f = (float*)smx;
#pragma unroll
    for (int mt = 0; mt < 2; mt++)
#pragma unroll
        for (int nt = 0; nt < 8; nt++) {
            int row = wm * 32 + mt * 16 + (lane >> 2);
            int col = wn * 64 + nt * 8 + 2 * (lane & 3);
            h2f[row * 260 + col]     = lsig(acc[mt][nt][0]);
            h2f[row * 260 + col + 1] = lsig(acc[mt][nt][1]);
            h2f[(row + 8) * 260 + col]     = lsig(acc[mt][nt][2]);
            h2f[(row + 8) * 260 + col + 1] = lsig(acc[mt][nt][3]);
        }
    __syncthreads();

    // coalesced vector-RED scatter
    for (int i = tid; i < 128 * 64; i += 512) {
        int row = i >> 6, seg = i & 63;
        if (ebase + row < (size_t)E_N) {
            float4 v = *(float4*)(h2f + row * 260 + seg * 4);
            atomicAdd((float4*)(g_agg + (size_t)svi[row] * 256 + seg * 4), v);
        }
    }
}

// ---------------- var kernel: g_agg -> MLP(256,256,128) -> classifier(128,2) ----------------
__global__ __launch_bounds__(512, 1) void var_kernel(
    const float* __restrict__ b1a, const float* __restrict__ Wc,
    const float* __restrict__ bc, float* __restrict__ out)
{
    extern __shared__ char smx[];
    uint32_t sb = smem_u32_of(smx);
    const int tid = threadIdx.x, lane = tid & 31, wid = tid >> 5;
    const int wm = wid & 3, wn = wid >> 2;
    const size_t vb = (size_t)blockIdx.x * 128;
    float* bias = (float*)(smx + BIAS_OFF);
    float* wc = (float*)(smx + AUX_OFF);

    if (tid < 128) {
        ((float2*)bias)[tid] = ((const float2*)b1a)[tid];
        ((float2*)wc)[tid]   = ((const float2*)Wc)[tid];
    }

    // ---- stage A = g_agg rows hi/lo into [128][520] ----
    for (int idx = tid; idx < 128 * 128; idx += 512) {
        int row = idx >> 7, p = idx & 127, c0 = 2 * p;
        size_t gv = vb + row;
        float2 t = (gv < (size_t)V_N) ? *(const float2*)(g_agg + gv * 256 + c0)
                                      : make_float2(0.f, 0.f);
        uint32_t hh, ll;
        cvt2(t.x, t.y, hh, ll);
        *(uint32_t*)(smx + (row * 520 + c0) * 2) = hh;
        *(uint32_t*)(smx + (row * 520 + 256 + c0) * 2) = ll;
    }

    float acc[2][8][4];
#pragma unroll
    for (int i = 0; i < 2; i++)
#pragma unroll
        for (int j = 0; j < 8; j++)
#pragma unroll
            for (int q = 0; q < 4; q++) acc[i][j][q] = 0.f;

    // GEMM1: K=256, NC=8
    gemm3<8>(g_w1a_p, 256, 8, 256, sb, 520, sb + B_OFF, wm, wn, lane, tid, acc);
    epi_h1(acc, bias, smx, wm, wn, lane);

    // GEMM2: N=128, K=256 (warp tile 32x32)
    float acc2[2][4][4];
#pragma unroll
    for (int i = 0; i < 2; i++)
#pragma unroll
        for (int j = 0; j < 4; j++)
#pragma unroll
            for (int q = 0; q < 4; q++) acc2[i][j][q] = 0.f;
    gemm3<4>(g_w2a_p, 256, 8, 128, sb, 520, sb + B_OFF, wm, wn, lane, tid, acc2);

    // epilogue: lsig -> fp32 h2 [128][132]
    float* h2f = (float*)smx;
#pragma unroll
    for (int mt = 0; mt < 2; mt++)
#pragma unroll
        for (int nt = 0; nt < 4; nt++) {
            int row = wm * 32 + mt * 16 + (lane >> 2);
            int col = wn * 32 + nt * 8 + 2 * (lane & 3);
            h2f[row * 132 + col]     = lsig(acc2[mt][nt][0]);
            h2f[row * 132 + col + 1] = lsig(acc2[mt][nt][1]);
            h2f[(row + 8) * 132 + col]     = lsig(acc2[mt][nt][2]);
            h2f[(row + 8) * 132 + col + 1] = lsig(acc2[mt][nt][3]);
        }
    __syncthreads();

    // classifier: out[row] = Wc @ h2row + bc  (256 threads cover 128 rows x 2)
    if (tid < 256) {
        int row = tid >> 1, p = tid & 1;
        float s = __ldg(bc + p);
        const float* wcp = wc + p * 128;
        const float* hr = h2f + row * 132;
#pragma unroll 8
        for (int j = 0; j < 128; j++) s = fmaf(hr[j], wcp[j], s);
        size_t gv = vb + row;
        if (gv < (size_t)V_N) out[gv * 2 + p] = s;
    }
}

// ---------------- launch ----------------
extern "C" void kernel_launch(void* const* d_in, const int* in_sizes, int n_in,
                              void* d_out, int out_size)
{
    const float* vs   = (const float*)d_in[0];
    const float* ef   = (const float*)d_in[1];
    const float* sol  = (const float*)d_in[2];
    const float* W1m  = (const float*)d_in[3];
    const float* b1m  = (const float*)d_in[4];
    const float* W2m  = (const float*)d_in[5];
    const float* W1a  = (const float*)d_in[6];
    const float* b1a  = (const float*)d_in[7];
    const float* W2a  = (const float*)d_in[8];
    const float* Wc   = (const float*)d_in[9];
    const float* bc   = (const float*)d_in[10];
    const int*  vidx  = (const int*)d_in[11];
    const int*  esign = (const int*)d_in[12];
    float* out = (float*)d_out;

    cudaFuncSetAttribute(edge_kernel, cudaFuncAttributeMaxDynamicSharedMemorySize, SMEM_TOTAL);
    cudaFuncSetAttribute(var_kernel,  cudaFuncAttributeMaxDynamicSharedMemorySize, SMEM_TOTAL);

    prep_w_kernel<<<(256 * 160 + 255) / 256, 256>>>(W1m, 0, 256, 145, 160);
    prep_w_kernel<<<(256 * 256 + 255) / 256, 256>>>(W2m, 1, 256, 256, 256);
    prep_w_kernel<<<(256 * 256 + 255) / 256, 256>>>(W1a, 2, 256, 256, 256);
    prep_w_kernel<<<(128 * 256 + 255) / 256, 256>>>(W2a, 3, 128, 256, 256);
    zero_agg_kernel<<<50000, 256>>>();
    edge_kernel<<<(E_N + 127) / 128, 512, SMEM_TOTAL>>>(vs, ef, sol, b1m, vidx, esign);
    var_kernel<<<(V_N + 127) / 128, 512, SMEM_TOTAL>>>(b1a, Wc, bc, out);
}